// round 6
// baseline (speedup 1.0000x reference)
#include <cuda_runtime.h>
#include <cuda_fp16.h>
#include <cstdint>

#define N_ROWS 8192
#define IN_F   2048
#define OUT_F  2048

// ---------------- static device scratch ----------------
__device__ __half g_a [N_ROWS * IN_F];   // input  (fp16)
__device__ __half g_bt[OUT_F * IN_F];    // Ht[n][k] = H[k][n] (fp16)

// H[k][n] = s * weight[k/4][comp*512 + n/4]; index = (k%4)*4 + (n%4)
__constant__ unsigned char c_comp[16] = {0,1,2,3, 1,0,3,2, 2,3,0,1, 3,2,1,0};
__constant__ unsigned char c_neg [16] = {0,1,1,1, 0,0,1,0, 0,0,0,1, 0,1,0,0};

// ---------------- prep kernels ----------------
__global__ void convert_input_kernel(const float* __restrict__ in) {
    int i = blockIdx.x * blockDim.x + threadIdx.x;
    const int total4 = N_ROWS * IN_F / 4;
    if (i >= total4) return;
    float4 v = reinterpret_cast<const float4*>(in)[i];
    __half2 h0 = __floats2half2_rn(v.x, v.y);
    __half2 h1 = __floats2half2_rn(v.z, v.w);
    uint2 o;
    o.x = reinterpret_cast<uint32_t&>(h0);
    o.y = reinterpret_cast<uint32_t&>(h1);
    reinterpret_cast<uint2*>(g_a)[i] = o;
}

__global__ void build_ht_kernel(const float* __restrict__ w) {
    int idx = blockIdx.x * blockDim.x + threadIdx.x;
    if (idx >= OUT_F * IN_F) return;
    int n = idx >> 11;        // IN_F = 2048
    int k = idx & 2047;
    int t = (k & 3) * 4 + (n & 3);
    int c = c_comp[t];
    float val = __ldg(&w[(k >> 2) * OUT_F + c * 512 + (n >> 2)]);
    if (c_neg[t]) val = -val;
    g_bt[idx] = __float2half_rn(val);
}

// ---------------- PTX helpers ----------------
__device__ __forceinline__ uint32_t smem_u32(const void* p) {
    uint32_t a;
    asm("{ .reg .u64 t; cvta.to.shared.u64 t, %1; cvt.u32.u64 %0, t; }" : "=r"(a) : "l"(p));
    return a;
}

#define CP_ASYNC16(dst, src) \
    asm volatile("cp.async.cg.shared.global [%0], [%1], 16;" :: "r"(dst), "l"(src))
#define CP_COMMIT() asm volatile("cp.async.commit_group;")
#define CP_WAIT(n)  asm volatile("cp.async.wait_group %0;" :: "n"(n))

__device__ __forceinline__ void ldsm_x4(uint32_t& r0, uint32_t& r1, uint32_t& r2, uint32_t& r3,
                                        uint32_t addr) {
    asm volatile("ldmatrix.sync.aligned.m8n8.x4.shared.b16 {%0,%1,%2,%3}, [%4];"
                 : "=r"(r0), "=r"(r1), "=r"(r2), "=r"(r3) : "r"(addr));
}

__device__ __forceinline__ void hmma(float* c, const uint32_t* a, uint32_t b0, uint32_t b1) {
    asm volatile(
        "mma.sync.aligned.m16n8k16.row.col.f32.f16.f16.f32 "
        "{%0,%1,%2,%3}, {%4,%5,%6,%7}, {%8,%9}, {%0,%1,%2,%3};"
        : "+f"(c[0]), "+f"(c[1]), "+f"(c[2]), "+f"(c[3])
        : "r"(a[0]), "r"(a[1]), "r"(a[2]), "r"(a[3]), "r"(b0), "r"(b1));
}

// ---------------- GEMM config ----------------
#define BM 128
#define BN 128
#define BK 64                 // per stage (two 32-k chunks)
#define STAGES 4
#define THREADS 256
#define KTILES (IN_F / BK)    // 32

static constexpr int CHUNK_B = BM * 32 * 2;     // 8192 bytes per 32-k fp16 chunk
static constexpr int OP_B    = 2 * CHUNK_B;     // 16 KB per operand per stage
static constexpr int STAGE_B = 2 * OP_B;        // A + B = 32 KB
static constexpr int SMEM_TOTAL = STAGES * STAGE_B;  // 128 KB

// Chunks stored as [row][32 k] = 64B rows, 4x 16B chunks; swizzle: chunk ^= (row>>1)&3
__global__ void __launch_bounds__(THREADS, 1) qlinear_gemm(
    const float* __restrict__ bias, float* __restrict__ out)
{
    extern __shared__ char smem[];
    const uint32_t sbase = smem_u32(smem);
    const int tid  = threadIdx.x;
    const int wid  = tid >> 5;
    const int lane = tid & 31;
    const int warp_m = wid & 3;    // 4 warps along M -> 32 rows each
    const int warp_n = wid >> 2;   // 2 warps along N -> 64 cols each
    const int m0 = blockIdx.y * BM;
    const int n0 = blockIdx.x * BN;

    // ---- cp.async addressing: per stage, per operand: 2 chunks; thread moves 2x16B/chunk
    const __half* gt[2] = {
        g_a  + (size_t)m0 * IN_F,
        g_bt + (size_t)n0 * IN_F
    };
    const int lr = tid >> 2;             // row 0..63 (second half row+64)
    const int lc = tid & 3;              // 16B chunk col 0..3
    const uint32_t dst_off = lr * 64 + ((lc ^ ((lr >> 1) & 3)) << 4);
    const size_t src_off = (size_t)lr * IN_F + lc * 8;  // elements

    // ---- ldmatrix per-lane addressing ----
    const int g = lane >> 3, r = lane & 7;
    uint32_t a_row[2], a_sw[2];
    const int a_gbit = g >> 1;
#pragma unroll
    for (int mt = 0; mt < 2; ++mt) {
        int row = warp_m * 32 + mt * 16 + (g & 1) * 8 + r;
        a_row[mt] = row * 64;
        a_sw[mt]  = (row >> 1) & 3;
    }
    uint32_t b_row[4], b_sw[4];
    const int b_gbit = g & 1;
#pragma unroll
    for (int np = 0; np < 4; ++np) {
        int row = warp_n * 64 + np * 16 + (g >> 1) * 8 + r;
        b_row[np] = row * 64;
        b_sw[np]  = (row >> 1) & 3;
    }

    float acc[2][8][4];
#pragma unroll
    for (int mt = 0; mt < 2; ++mt)
#pragma unroll
        for (int nt = 0; nt < 8; ++nt)
#pragma unroll
            for (int e = 0; e < 4; ++e) acc[mt][nt][e] = 0.0f;

    // ---- stage loader: 8 x 16B per thread ----
    auto load_stage = [&](int s) {
        const int kc = s * BK;
        const uint32_t sb = sbase + (s & (STAGES - 1)) * STAGE_B;
#pragma unroll
        for (int t = 0; t < 2; ++t) {
#pragma unroll
            for (int c = 0; c < 2; ++c) {
                const __half* gsrc = gt[t] + kc + c * 32 + src_off;
                uint32_t d = sb + t * OP_B + c * CHUNK_B + dst_off;
                CP_ASYNC16(d,        gsrc);
                CP_ASYNC16(d + 4096, gsrc + (size_t)64 * IN_F);
            }
        }
    };

    // fragment double buffers
    uint32_t ah[2][2][4], bh[2][4][4];

    // frag loader for k16-substep sk (0..3) of stage base sb into buffer bb
    auto load_frags = [&](int bb, uint32_t sb, int sk) {
        const uint32_t abase = sb + (sk >> 1) * CHUNK_B;
        const uint32_t bbase = sb + OP_B + (sk >> 1) * CHUNK_B;
        const uint32_t ca = (uint32_t)(2 * (sk & 1) + a_gbit);
        const uint32_t cb = (uint32_t)(2 * (sk & 1) + b_gbit);
#pragma unroll
        for (int mt = 0; mt < 2; ++mt) {
            uint32_t off = a_row[mt] + ((ca ^ a_sw[mt]) << 4);
            ldsm_x4(ah[bb][mt][0], ah[bb][mt][1], ah[bb][mt][2], ah[bb][mt][3], abase + off);
        }
#pragma unroll
        for (int np = 0; np < 4; ++np) {
            uint32_t off = b_row[np] + ((cb ^ b_sw[np]) << 4);
            ldsm_x4(bh[bb][np][0], bh[bb][np][1], bh[bb][np][2], bh[bb][np][3], bbase + off);
        }
    };

    // prologue: 3 stages in flight
#pragma unroll
    for (int s = 0; s < STAGES - 1; ++s) { load_stage(s); CP_COMMIT(); }

    for (int s = 0; s < KTILES; ++s) {
        CP_WAIT(STAGES - 2);
        __syncthreads();
        if (s + STAGES - 1 < KTILES) load_stage(s + STAGES - 1);
        CP_COMMIT();

        const uint32_t sb = sbase + (s & (STAGES - 1)) * STAGE_B;
        load_frags(0, sb, 0);
#pragma unroll
        for (int sk = 0; sk < 4; ++sk) {
            const int cur = sk & 1;
            if (sk < 3) load_frags(cur ^ 1, sb, sk + 1);
#pragma unroll
            for (int mt = 0; mt < 2; ++mt) {
#pragma unroll
                for (int nt = 0; nt < 8; ++nt) {
                    const int np = nt >> 1, sel = (nt & 1) * 2;
                    hmma(acc[mt][nt], ah[cur][mt], bh[cur][np][sel], bh[cur][np][sel + 1]);
                }
            }
        }
    }

    // ---- epilogue: add bias, store fp32 ----
#pragma unroll
    for (int mt = 0; mt < 2; ++mt) {
        int row = m0 + warp_m * 32 + mt * 16 + (lane >> 2);
#pragma unroll
        for (int nt = 0; nt < 8; ++nt) {
            int col = n0 + warp_n * 64 + nt * 8 + (lane & 3) * 2;
            float bx = __ldg(&bias[col]);
            float by = __ldg(&bias[col + 1]);
            float2 v0 = {acc[mt][nt][0] + bx, acc[mt][nt][1] + by};
            float2 v1 = {acc[mt][nt][2] + bx, acc[mt][nt][3] + by};
            *reinterpret_cast<float2*>(out + (size_t)row * OUT_F + col) = v0;
            *reinterpret_cast<float2*>(out + (size_t)(row + 8) * OUT_F + col) = v1;
        }
    }
}

// ---------------- launch ----------------
extern "C" void kernel_launch(void* const* d_in, const int* in_sizes, int n_in,
                              void* d_out, int out_size) {
    (void)in_sizes; (void)n_in; (void)out_size;
    const float* input  = (const float*)d_in[0];
    const float* weight = (const float*)d_in[1];
    const float* bias   = (const float*)d_in[2];
    float* out = (float*)d_out;

    cudaFuncSetAttribute(qlinear_gemm, cudaFuncAttributeMaxDynamicSharedMemorySize, SMEM_TOTAL);

    {
        int total4 = N_ROWS * IN_F / 4;
        convert_input_kernel<<<(total4 + 255) / 256, 256>>>(input);
    }
    {
        int total = OUT_F * IN_F;
        build_ht_kernel<<<(total + 255) / 256, 256>>>(weight);
    }
    qlinear_gemm<<<dim3(OUT_F / BN, N_ROWS / BM), THREADS, SMEM_TOTAL>>>(bias, out);
}

// round 9
// speedup vs baseline: 1.7448x; 1.7448x over previous
#include <cuda_runtime.h>
#include <cuda_fp16.h>
#include <cstdint>

#define N_ROWS 8192
#define IN_F   2048
#define OUT_F  2048
#define XN     512            // combo width (quaternion group count)
#define NPROD  8

static constexpr size_t NT = (size_t)N_ROWS * XN;   // elems per X-combo / t-product

// ---------------- static device scratch ----------------
__device__ __half g_xc[NPROD * NT];          // 8 X-combos  [8192 x 512] fp16 (64 MB)
__device__ __half g_wt[NPROD * XN * XN];     // 8 W-combos  [512 x 512]  fp16, [nu][kappa] (4 MB)
__device__ float  g_t [NPROD * NT];          // 8 products  [8192 x 512] fp32 (128 MB)

// ---------------- prep: X combos ----------------
// X_a[m][kap] = in[m][4*kap + a];  one float4 read yields all 4 comps.
__global__ void make_xc_kernel(const float* __restrict__ in) {
    size_t idx = (size_t)blockIdx.x * blockDim.x + threadIdx.x;
    if (idx >= NT) return;
    float4 v = reinterpret_cast<const float4*>(in)[idx];  // (X0,X1,X2,X3)
    g_xc[0 * NT + idx] = __float2half_rn(v.x + v.y);  // t0: X0+X1
    g_xc[1 * NT + idx] = __float2half_rn(v.z - v.w);  // t1: X2-X3
    g_xc[2 * NT + idx] = __float2half_rn(v.z + v.w);  // t2: X2+X3
    g_xc[3 * NT + idx] = __float2half_rn(v.x - v.y);  // t3: X0-X1
    g_xc[4 * NT + idx] = __float2half_rn(v.y + v.z);  // v4: X1+X2
    g_xc[5 * NT + idx] = __float2half_rn(v.y - v.z);  // v5: X1-X2
    g_xc[6 * NT + idx] = __float2half_rn(v.x - v.w);  // v6: X0-X3
    g_xc[7 * NT + idx] = __float2half_rn(v.x + v.w);  // v7: X0+X3
}

// ---------------- prep: W combos (transposed to [nu][kappa]) ----------------
// W_c[kap][nu] = w[kap*2048 + c*512 + nu]. 32x32 smem tile transpose.
__global__ void make_wc_kernel(const float* __restrict__ w) {
    __shared__ __half tile[NPROD][32][33];
    const int kap0 = blockIdx.x * 32;
    const int nu0  = blockIdx.y * 32;
    const int tid = threadIdx.x;           // 256 threads
    for (int p = 0; p < 4; ++p) {
        int r = p * 8 + (tid >> 5);        // kap offset 0..31
        int cnu = tid & 31;                // nu offset
        const float* wr = w + (size_t)(kap0 + r) * OUT_F + nu0 + cnu;
        float b0 = wr[0], b1 = wr[512], b2 = wr[1024], b3 = wr[1536];
        tile[0][r][cnu] = __float2half_rn(b0 - b1);
        tile[1][r][cnu] = __float2half_rn(b2 - b3);
        tile[2][r][cnu] = __float2half_rn(b0 + b1);
        tile[3][r][cnu] = __float2half_rn(b2 + b3);
        tile[4][r][cnu] = __float2half_rn(0.5f * (b1 + b3));
        tile[5][r][cnu] = __float2half_rn(0.5f * (b1 - b3));
        tile[6][r][cnu] = __float2half_rn(0.5f * (b0 - b2));
        tile[7][r][cnu] = __float2half_rn(0.5f * (b0 + b2));
    }
    __syncthreads();
    for (int p = 0; p < 4; ++p) {
        int rnu = p * 8 + (tid >> 5);
        int ck  = tid & 31;
#pragma unroll
        for (int i = 0; i < NPROD; ++i) {
            g_wt[(size_t)i * XN * XN + (size_t)(nu0 + rnu) * XN + kap0 + ck] = tile[i][ck][rnu];
        }
    }
}

// ---------------- PTX helpers ----------------
__device__ __forceinline__ uint32_t smem_u32(const void* p) {
    uint32_t a;
    asm("{ .reg .u64 t; cvta.to.shared.u64 t, %1; cvt.u32.u64 %0, t; }" : "=r"(a) : "l"(p));
    return a;
}

#define CP_ASYNC16(dst, src) \
    asm volatile("cp.async.cg.shared.global [%0], [%1], 16;" :: "r"(dst), "l"(src))
#define CP_COMMIT() asm volatile("cp.async.commit_group;")
#define CP_WAIT(n)  asm volatile("cp.async.wait_group %0;" :: "n"(n))

__device__ __forceinline__ void ldsm_x4(uint32_t& r0, uint32_t& r1, uint32_t& r2, uint32_t& r3,
                                        uint32_t addr) {
    asm volatile("ldmatrix.sync.aligned.m8n8.x4.shared.b16 {%0,%1,%2,%3}, [%4];"
                 : "=r"(r0), "=r"(r1), "=r"(r2), "=r"(r3) : "r"(addr));
}

__device__ __forceinline__ void hmma(float* c, const uint32_t* a, uint32_t b0, uint32_t b1) {
    asm volatile(
        "mma.sync.aligned.m16n8k16.row.col.f32.f16.f16.f32 "
        "{%0,%1,%2,%3}, {%4,%5,%6,%7}, {%8,%9}, {%0,%1,%2,%3};"
        : "+f"(c[0]), "+f"(c[1]), "+f"(c[2]), "+f"(c[3])
        : "r"(a[0]), "r"(a[1]), "r"(a[2]), "r"(a[3]), "r"(b0), "r"(b1));
}

// ---------------- batched GEMM: t_z = XC_z [8192x512] @ WT_z [512x512]^T ----------------
#define BM 128
#define BN 128
#define BK 64
#define STAGES 3
#define THREADS 256
#define KTILES (XN / BK)      // 8

static constexpr int CHUNK_B = BM * 32 * 2;     // 8192 B per 32-k fp16 chunk
static constexpr int OP_B    = 2 * CHUNK_B;     // 16 KB per operand per stage
static constexpr int STAGE_B = 2 * OP_B;        // 32 KB
static constexpr int SMEM_TOTAL = STAGES * STAGE_B;  // 96 KB

__global__ void __launch_bounds__(THREADS, 2) qprod_gemm()
{
    extern __shared__ char smem[];
    const uint32_t sbase = smem_u32(smem);
    const int tid  = threadIdx.x;
    const int wid  = tid >> 5;
    const int lane = tid & 31;
    const int warp_m = wid & 3;
    const int warp_n = wid >> 2;
    const int m0 = blockIdx.y * BM;
    const int n0 = blockIdx.x * BN;
    const int z  = blockIdx.z;

    const __half* gA = g_xc + (size_t)z * NT + (size_t)m0 * XN;
    const __half* gB = g_wt + (size_t)z * XN * XN + (size_t)n0 * XN;
    float* gT = g_t + (size_t)z * NT;

    const int lr = tid >> 2;             // row 0..63 (+64 second half)
    const int lc = tid & 3;              // 16B chunk col
    const uint32_t dst_off = lr * 64 + ((lc ^ ((lr >> 1) & 3)) << 4);
    const size_t src_off = (size_t)lr * XN + lc * 8;

    const int g = lane >> 3, r = lane & 7;
    uint32_t a_row[2], a_sw[2];
    const int a_gbit = g >> 1;
#pragma unroll
    for (int mt = 0; mt < 2; ++mt) {
        int row = warp_m * 32 + mt * 16 + (g & 1) * 8 + r;
        a_row[mt] = row * 64;
        a_sw[mt]  = (row >> 1) & 3;
    }
    uint32_t b_row[4], b_sw[4];
    const int b_gbit = g & 1;
#pragma unroll
    for (int np = 0; np < 4; ++np) {
        int row = warp_n * 64 + np * 16 + (g >> 1) * 8 + r;
        b_row[np] = row * 64;
        b_sw[np]  = (row >> 1) & 3;
    }

    float acc[2][8][4];
#pragma unroll
    for (int mt = 0; mt < 2; ++mt)
#pragma unroll
        for (int nt = 0; nt < 8; ++nt)
#pragma unroll
            for (int e = 0; e < 4; ++e) acc[mt][nt][e] = 0.0f;

    int slot_of[KTILES + STAGES];
#pragma unroll
    for (int s = 0; s < KTILES + STAGES; ++s) slot_of[s] = s % STAGES;

    auto load_stage = [&](int s) {
        const int kc = s * BK;
        const uint32_t sb = sbase + slot_of[s] * STAGE_B;
        {
            const __half* asrc = gA + kc + src_off;
            const __half* bsrc = gB + kc + src_off;
#pragma unroll
            for (int c = 0; c < 2; ++c) {
                uint32_t da = sb + c * CHUNK_B + dst_off;
                uint32_t db = sb + OP_B + c * CHUNK_B + dst_off;
                CP_ASYNC16(da,        asrc + c * 32);
                CP_ASYNC16(da + 4096, asrc + c * 32 + (size_t)64 * XN);
                CP_ASYNC16(db,        bsrc + c * 32);
                CP_ASYNC16(db + 4096, bsrc + c * 32 + (size_t)64 * XN);
            }
        }
    };

    // prologue: 2 stages in flight
    load_stage(0); CP_COMMIT();
    load_stage(1); CP_COMMIT();

    for (int s = 0; s < KTILES; ++s) {
        CP_WAIT(1);
        __syncthreads();
        if (s + 2 < KTILES) load_stage(s + 2);
        CP_COMMIT();

        const uint32_t sb = sbase + slot_of[s] * STAGE_B;
#pragma unroll
        for (int sk = 0; sk < 4; ++sk) {
            const uint32_t abase = sb + (sk >> 1) * CHUNK_B;
            const uint32_t bbase = sb + OP_B + (sk >> 1) * CHUNK_B;
            const uint32_t ca = (uint32_t)(2 * (sk & 1) + a_gbit);
            const uint32_t cb = (uint32_t)(2 * (sk & 1) + b_gbit);
            uint32_t ah[2][4], bh[4][4];
#pragma unroll
            for (int mt = 0; mt < 2; ++mt) {
                uint32_t off = a_row[mt] + ((ca ^ a_sw[mt]) << 4);
                ldsm_x4(ah[mt][0], ah[mt][1], ah[mt][2], ah[mt][3], abase + off);
            }
#pragma unroll
            for (int np = 0; np < 4; ++np) {
                uint32_t off = b_row[np] + ((cb ^ b_sw[np]) << 4);
                ldsm_x4(bh[np][0], bh[np][1], bh[np][2], bh[np][3], bbase + off);
            }
#pragma unroll
            for (int mt = 0; mt < 2; ++mt) {
#pragma unroll
                for (int nt = 0; nt < 8; ++nt) {
                    const int np = nt >> 1, sel = (nt & 1) * 2;
                    hmma(acc[mt][nt], ah[mt], bh[np][sel], bh[np][sel + 1]);
                }
            }
        }
    }

    // ---- epilogue: store t (fp32, pitch 512) ----
#pragma unroll
    for (int mt = 0; mt < 2; ++mt) {
        int row = m0 + warp_m * 32 + mt * 16 + (lane >> 2);
#pragma unroll
        for (int nt = 0; nt < 8; ++nt) {
            int col = n0 + warp_n * 64 + nt * 8 + (lane & 3) * 2;
            float2 v0 = {acc[mt][nt][0], acc[mt][nt][1]};
            float2 v1 = {acc[mt][nt][2], acc[mt][nt][3]};
            *reinterpret_cast<float2*>(gT + (size_t)row * XN + col) = v0;
            *reinterpret_cast<float2*>(gT + (size_t)(row + 8) * XN + col) = v1;
        }
    }
}

// ---------------- combine: O from 8 products + bias ----------------
// T4+T5 = X1W1+X2W3   T4-T5 = X1W3+X2W1
// T6+T7 = X0W0+X3W2   T6-T7 = -X0W2-X3W0
// O0 = T1 + (T4+T5) + (T6+T7)
// O1 = T0 + (T4+T5) - (T6+T7)
// O2 = T2 - (T4-T5) + (T6-T7)
// O3 = -T3 - (T4-T5) - (T6-T7)
__global__ void combine_kernel(const float* __restrict__ bias, float* __restrict__ out) {
    size_t idx = (size_t)blockIdx.x * blockDim.x + threadIdx.x;
    if (idx >= NT) return;
    float T0 = g_t[0 * NT + idx];
    float T1 = g_t[1 * NT + idx];
    float T2 = g_t[2 * NT + idx];
    float T3 = g_t[3 * NT + idx];
    float T4 = g_t[4 * NT + idx];
    float T5 = g_t[5 * NT + idx];
    float T6 = g_t[6 * NT + idx];
    float T7 = g_t[7 * NT + idx];
    float s1 = T4 + T5, s2 = T6 + T7;
    float d1 = T4 - T5, d2 = T6 - T7;
    int nu = (int)(idx & 511);
    float4 b = reinterpret_cast<const float4*>(bias)[nu];
    float4 o;
    o.x =  T1 + s1 + s2 + b.x;
    o.y =  T0 + s1 - s2 + b.y;
    o.z =  T2 - d1 + d2 + b.z;
    o.w = -T3 - d1 - d2 + b.w;
    reinterpret_cast<float4*>(out)[idx] = o;
}

// ---------------- launch ----------------
extern "C" void kernel_launch(void* const* d_in, const int* in_sizes, int n_in,
                              void* d_out, int out_size) {
    (void)in_sizes; (void)n_in; (void)out_size;
    const float* input  = (const float*)d_in[0];
    const float* weight = (const float*)d_in[1];
    const float* bias   = (const float*)d_in[2];
    float* out = (float*)d_out;

    cudaFuncSetAttribute(qprod_gemm, cudaFuncAttributeMaxDynamicSharedMemorySize, SMEM_TOTAL);

    make_xc_kernel<<<(unsigned)((NT + 255) / 256), 256>>>(input);
    make_wc_kernel<<<dim3(XN / 32, XN / 32), 256>>>(weight);
    qprod_gemm<<<dim3(XN / BN, N_ROWS / BM, NPROD), THREADS, SMEM_TOTAL>>>();
    combine_kernel<<<(unsigned)((NT + 255) / 256), 256>>>(bias, out);
}